// round 2
// baseline (speedup 1.0000x reference)
#include <cuda_runtime.h>

#define B_ 1024
#define T_ 512
#define K_ 48
#define NEG_ (-10000.0f)
#define START_ 46
#define STOP_ 47

__device__ __forceinline__ float neg_inf() { return __int_as_float(0xff800000); }

__global__ __launch_bounds__(64, 7)
void crf_kernel(const float* __restrict__ feats,
                const float* __restrict__ trans,
                const int* __restrict__ tags,
                float* __restrict__ out)
{
    const int b    = blockIdx.x;
    const int j    = threadIdx.x;   // state index (j<48 active states)
    const int lane = j & 31;
    const int wid  = j >> 5;

    __shared__ float sh_a[64];
    __shared__ float sh_v[64];
    __shared__ float sh_red[2];
    __shared__ float sh_red2[2];
    __shared__ unsigned char bp[T_ * K_];   // 24576 B backpointers

    const float* frow = feats + (size_t)b * (T_ * K_);
    const int*   trow = tags  + b * T_;

    // ---- per-thread transition row (masked) in registers ----
    float E[K_], Tr[K_];
    {
        int row = (j < K_) ? j : 0;
        #pragma unroll
        for (int p = 0; p < K_; p++) {
            float tv = trans[row * K_ + p];
            if (row == START_) tv = NEG_;   // never INTO start
            if (p == STOP_)    tv = NEG_;   // never OUT OF stop
            Tr[p] = tv;
            E[p]  = __expf(tv);             // exp(-10000) -> exactly 0
        }
    }

    // ---- gold score (raw trans: mask never touched on gold path) ----
    float gold_part = 0.0f;
    for (int t = j; t < T_; t += 64) {
        int tg = trow[t];
        int pv = (t == 0) ? START_ : trow[t - 1];
        gold_part += frow[t * K_ + tg] + trans[tg * K_ + pv];
    }
    #pragma unroll
    for (int o = 16; o > 0; o >>= 1)
        gold_part += __shfl_xor_sync(0xffffffffu, gold_part, o);
    if (lane == 0) sh_red[wid] = gold_part;
    __syncthreads();
    float gold = sh_red[0] + sh_red[1]
               + trans[STOP_ * K_ + trow[T_ - 1]];
    __syncthreads();

    // ---- init ----
    float alpha, v;
    if (j < K_) alpha = (j == START_) ? 0.0f : NEG_;
    else        alpha = neg_inf();
    v = alpha;

    // ---- main recurrence ----
    for (int t = 0; t < T_; t++) {
        float emit = (j < K_) ? frow[t * K_ + j] : neg_inf();

        // block max of alpha (stability shift; exact max not required)
        float wa = alpha;
        #pragma unroll
        for (int o = 16; o > 0; o >>= 1)
            wa = fmaxf(wa, __shfl_xor_sync(0xffffffffu, wa, o));
        if (lane == 0) sh_red[wid] = wa;
        __syncthreads();
        float m = fmaxf(sh_red[0], sh_red[1]);

        sh_a[j] = __expf(alpha - m);   // -inf -> 0
        sh_v[j] = v;
        __syncthreads();

        float sum  = 0.0f;
        float best = neg_inf();
        int   bi   = 0;
        const float4* a4 = (const float4*)sh_a;
        const float4* v4 = (const float4*)sh_v;
        #pragma unroll
        for (int q = 0; q < K_ / 4; q++) {
            float4 av = a4[q];
            float4 vv = v4[q];
            sum = fmaf(E[4*q+0], av.x, sum);
            sum = fmaf(E[4*q+1], av.y, sum);
            sum = fmaf(E[4*q+2], av.z, sum);
            sum = fmaf(E[4*q+3], av.w, sum);
            // strictly-greater update == jnp first-max argmax; adds bitwise
            // identical to reference -> exact path reproduction
            float s0 = vv.x + Tr[4*q+0];
            if (s0 > best) { best = s0; bi = 4*q+0; }
            float s1 = vv.y + Tr[4*q+1];
            if (s1 > best) { best = s1; bi = 4*q+1; }
            float s2 = vv.z + Tr[4*q+2];
            if (s2 > best) { best = s2; bi = 4*q+2; }
            float s3 = vv.w + Tr[4*q+3];
            if (s3 > best) { best = s3; bi = 4*q+3; }
        }
        alpha = emit + m + __logf(sum);   // log(0) -> -inf, propagates as 0-weight
        v     = best + emit;
        if (j < K_) bp[t * K_ + j] = (unsigned char)bi;
    }

    // ---- terminal transition into STOP ----
    float termTr;
    if (j >= K_)          termTr = neg_inf();
    else if (j == STOP_)  termTr = NEG_;               // [:,STOP] masked
    else                  termTr = trans[STOP_ * K_ + j];
    float fa = alpha + termTr;   // forward terminal
    float tv = v     + termTr;   // viterbi terminal

    // ---- logZ = LSE(fa) ----
    float wm = fa;
    #pragma unroll
    for (int o = 16; o > 0; o >>= 1)
        wm = fmaxf(wm, __shfl_xor_sync(0xffffffffu, wm, o));
    if (lane == 0) sh_red[wid] = wm;
    __syncthreads();
    float mm = fmaxf(sh_red[0], sh_red[1]);
    float ex = __expf(fa - mm);   // fa=-inf -> 0
    #pragma unroll
    for (int o = 16; o > 0; o >>= 1)
        ex += __shfl_xor_sync(0xffffffffu, ex, o);
    if (lane == 0) sh_red2[wid] = ex;
    __syncthreads();
    float logZ = mm + __logf(sh_red2[0] + sh_red2[1]);
    __syncthreads();

    // ---- viterbi terminal max + first-argmax ----
    float bmax = tv;
    #pragma unroll
    for (int o = 16; o > 0; o >>= 1)
        bmax = fmaxf(bmax, __shfl_xor_sync(0xffffffffu, bmax, o));
    if (lane == 0) sh_red[wid] = bmax;
    __syncthreads();
    float bm = fmaxf(sh_red[0], sh_red[1]);
    int cand = (tv == bm) ? j : (1 << 30);
    #pragma unroll
    for (int o = 16; o > 0; o >>= 1)
        cand = min(cand, __shfl_xor_sync(0xffffffffu, cand, o));
    if (lane == 0) sh_red2[wid] = __int_as_float(cand);
    __syncthreads();
    int best_last = min(__float_as_int(sh_red2[0]), __float_as_int(sh_red2[1]));

    // ---- outputs: [nll(B) | path_score(B) | paths(B*T)] as float32 ----
    if (j == 0) {
        out[b]      = logZ - gold;
        out[B_ + b] = bm;
        int tag = best_last;
        float* pout = out + 2 * B_ + (size_t)b * T_;
        for (int t = T_ - 1; t >= 0; t--) {
            pout[t] = (float)tag;
            tag = bp[t * K_ + tag];
        }
    }
}

extern "C" void kernel_launch(void* const* d_in, const int* in_sizes, int n_in,
                              void* d_out, int out_size) {
    const float* feats = (const float*)d_in[0];
    const float* trans = (const float*)d_in[1];
    const int*   tags  = (const int*)d_in[2];
    crf_kernel<<<B_, 64>>>(feats, trans, tags, (float*)d_out);
}

// round 3
// speedup vs baseline: 1.6151x; 1.6151x over previous
#include <cuda_runtime.h>

#define B_ 1024
#define T_ 512
#define K_ 48
#define NEG_ (-10000.0f)
#define START_ 46
#define STOP_ 47
#define NTHREADS 192
#define CHUNK 96

// scratch: v_t vectors for deferred backpointer recomputation (~100.7 MB)
__device__ float g_v[(size_t)B_ * T_ * K_];

__device__ __forceinline__ float neg_inf() { return __int_as_float(0xff800000); }

// order-preserving float->uint map (no NaNs in our data)
__device__ __forceinline__ unsigned fmono(float x) {
    unsigned u = __float_as_uint(x);
    return (u & 0x80000000u) ? ~u : (u | 0x80000000u);
}
__device__ __forceinline__ float funmono(unsigned k) {
    return __uint_as_float((k & 0x80000000u) ? (k & 0x7fffffffu) : ~k);
}

__global__ __launch_bounds__(NTHREADS, 7)
void crf_kernel(const float* __restrict__ feats,
                const float* __restrict__ trans,
                const int* __restrict__ tags,
                float* __restrict__ out)
{
    const int b    = blockIdx.x;
    const int tid  = threadIdx.x;
    const int j    = tid >> 2;     // state 0..47
    const int s    = tid & 3;      // slice 0..3 (p in [12s, 12s+12))
    const int lane = tid & 31;
    const int w    = tid >> 5;

    __shared__ float shTr[K_ * K_];       // masked transitions trans[next][prev]
    __shared__ float shA[2][K_];          // exp-domain forward (double buffered)
    __shared__ float shV[2][K_];          // viterbi scores     (double buffered)
    __shared__ float shRed[8];
    __shared__ float shChunk[CHUNK][K_];  // backtrace staging

    const float* frow = feats + (size_t)b * (T_ * K_);
    const int*   trow = tags + b * T_;
    float* gvb = g_v + (size_t)b * T_ * K_;

    // ---- masked transition slice into SMEM, exp(Tr) into registers ----
    float E[12];
    #pragma unroll
    for (int i = 0; i < 12; i++) {
        int p = 12 * s + i;
        float v = trans[j * K_ + p];
        if (j == START_) v = NEG_;   // never INTO start
        if (p == STOP_)  v = NEG_;   // never OUT OF stop
        shTr[j * K_ + p] = v;
        E[i] = __expf(v);            // exp(-10000) -> exactly 0
    }

    // ---- gold score (raw trans == masked on gold path) ----
    float gp = 0.f;
    for (int t = tid; t < T_; t += NTHREADS) {
        int tg = trow[t];
        int pv = (t == 0) ? START_ : trow[t - 1];
        gp += frow[t * K_ + tg] + trans[tg * K_ + pv];
    }
    #pragma unroll
    for (int o = 16; o; o >>= 1) gp += __shfl_xor_sync(~0u, gp, o);
    if (lane == 0) shRed[w] = gp;

    // ---- init recurrences ----
    if (tid < K_) {
        shA[0][tid] = (tid == START_) ? 1.0f : 0.0f;   // exp(alpha_init)
        shV[0][tid] = (tid == START_) ? 0.0f : NEG_;
    }
    __syncthreads();
    float gold = shRed[0] + shRed[1] + shRed[2] + shRed[3] + shRed[4] + shRed[5]
               + trans[STOP_ * K_ + trow[T_ - 1]];

    // ---- main recurrence: 1 sync/step, exp-domain forward, max-only viterbi ----
    double Md = 0.0;            // accumulated log of divided-out scale
    float scale = 1.0f;
    float emit_next = frow[j];
    const float4* TR4 = (const float4*)shTr;

    for (int t = 0; t < T_; t++) {
        float emit = emit_next;
        if (t < T_ - 1) emit_next = frow[(t + 1) * K_ + j];
        int cur = t & 1, nxt = cur ^ 1;
        const float4* A4 = (const float4*)shA[cur];
        const float4* V4 = (const float4*)shV[cur];

        float sum = 0.f;
        float vb  = neg_inf();
        #pragma unroll
        for (int q = 0; q < 3; q++) {
            float4 av = A4[3 * s + q];
            float4 vv = V4[3 * s + q];
            float4 tv = TR4[j * 12 + 3 * s + q];
            sum = fmaf(E[4*q+0], av.x, sum);
            sum = fmaf(E[4*q+1], av.y, sum);
            sum = fmaf(E[4*q+2], av.z, sum);
            sum = fmaf(E[4*q+3], av.w, sum);
            vb = fmaxf(vb, vv.x + tv.x);   // bitwise-identical adds vs reference
            vb = fmaxf(vb, vv.y + tv.y);
            vb = fmaxf(vb, vv.z + tv.z);
            vb = fmaxf(vb, vv.w + tv.w);
        }
        sum += __shfl_xor_sync(~0u, sum, 1);
        sum += __shfl_xor_sync(~0u, sum, 2);
        vb = fmaxf(vb, __shfl_xor_sync(~0u, vb, 1));
        vb = fmaxf(vb, __shfl_xor_sync(~0u, vb, 2));

        float anew = __expf(emit) * (sum * scale);
        float vnew = vb + emit;

        bool resc = ((t & 3) == 3) && (t != T_ - 1);
        if (resc) {
            float am = anew;
            am = fmaxf(am, __shfl_xor_sync(~0u, am, 4));
            am = fmaxf(am, __shfl_xor_sync(~0u, am, 8));
            am = fmaxf(am, __shfl_xor_sync(~0u, am, 16));
            if (lane == 0) shRed[w] = am;
        }
        if (s == 0) {
            shA[nxt][j] = anew;
            shV[nxt][j] = vnew;
            gvb[t * K_ + j] = vnew;       // stream v_t for backtrace
        }
        __syncthreads();
        if (resc) {
            float mx = fmaxf(fmaxf(fmaxf(shRed[0], shRed[1]), fmaxf(shRed[2], shRed[3])),
                             fmaxf(shRed[4], shRed[5]));
            int e = (int)((__float_as_uint(mx) >> 23) & 255) - 127;
            scale = __uint_as_float((unsigned)(127 - e) << 23);  // exact 2^-e
            Md += (double)e * 0.6931471805599453;
        } else {
            scale = 1.0f;
        }
    }
    // final buffers are index 0 (after t=511: nxt==0)

    // ---- logZ = Md + log( sum_j a_j * exp(termTr_j) ) ----
    float contrib = 0.f;
    if (s == 0) {
        float tt = shTr[STOP_ * K_ + j];   // masked: j==STOP -> NEG -> exp=0; a[START]=0
        contrib = shA[0][j] * __expf(tt);
    }
    #pragma unroll
    for (int o = 16; o; o >>= 1) contrib += __shfl_xor_sync(~0u, contrib, o);
    if (lane == 0) shRed[w] = contrib;
    __syncthreads();
    if (tid == 0) {
        float Z = shRed[0] + shRed[1] + shRed[2] + shRed[3] + shRed[4] + shRed[5];
        double logZ = Md + (double)logf(Z);
        out[b] = (float)(logZ - (double)gold);
    }

    // ---- viterbi terminal: first-argmax over 48 (exact, jnp semantics) ----
    int tag = 0;
    if (w == 0) {
        float x0 = shV[0][lane] + shTr[STOP_ * K_ + lane];
        float x1 = (lane < 16) ? shV[0][32 + lane] + shTr[STOP_ * K_ + 32 + lane]
                               : neg_inf();
        unsigned k0 = fmono(x0), k1 = fmono(x1);
        unsigned gm = __reduce_max_sync(~0u, (k0 > k1) ? k0 : k1);
        int cand = 1 << 30;
        if (k1 == gm) cand = 32 + lane;
        if (k0 == gm) cand = lane;      // lower p wins ties
        tag = __reduce_min_sync(~0u, cand);
        if (lane == 0) out[B_ + b] = funmono(gm);   // path_score = max(term)
    }

    // ---- backtrace: chunked SMEM staging of v history, warp0 walks path ----
    float* pout = out + 2 * B_ + (size_t)b * T_;
    const int NCH = (T_ + CHUNK - 1) / CHUNK;       // 6
    for (int c = NCH - 1; c >= 0; c--) {
        int lo = c * CHUNK;
        int hi = min(lo + CHUNK, T_);
        int r0 = max(lo - 1, 0);
        int r1 = hi - 1;                 // need rows [r0, r1)
        int base = lo - 1;
        int nq = (r1 - r0) * (K_ / 4);   // float4 count
        const float4* src = (const float4*)(gvb + (size_t)r0 * K_);
        float4* dst = (float4*)(&shChunk[r0 - base][0]);
        for (int i = tid; i < nq; i += NTHREADS) dst[i] = src[i];
        __syncthreads();
        if (w == 0) {
            for (int t = hi - 1; t >= lo; t--) {
                if (lane == 0) pout[t] = (float)tag;
                float pv0, pv1;
                if (t == 0) {
                    pv0 = (lane == START_) ? 0.f : NEG_;
                    pv1 = (32 + lane == START_) ? 0.f : NEG_;
                } else {
                    const float* row = shChunk[t - 1 - base];
                    pv0 = row[lane];
                    pv1 = (lane < 16) ? row[32 + lane] : 0.f;
                }
                float x0 = pv0 + shTr[tag * K_ + lane];
                float x1 = (lane < 16) ? pv1 + shTr[tag * K_ + 32 + lane]
                                       : neg_inf();
                unsigned k0 = fmono(x0), k1 = fmono(x1);
                unsigned gm = __reduce_max_sync(~0u, (k0 > k1) ? k0 : k1);
                int cand = 1 << 30;
                if (k1 == gm) cand = 32 + lane;
                if (k0 == gm) cand = lane;
                tag = __reduce_min_sync(~0u, cand);
            }
        }
        __syncthreads();
    }
}

extern "C" void kernel_launch(void* const* d_in, const int* in_sizes, int n_in,
                              void* d_out, int out_size) {
    const float* feats = (const float*)d_in[0];
    const float* trans = (const float*)d_in[1];
    const int*   tags  = (const int*)d_in[2];
    crf_kernel<<<B_, NTHREADS>>>(feats, trans, tags, (float*)d_out);
}

// round 4
// speedup vs baseline: 1.8932x; 1.1721x over previous
#include <cuda_runtime.h>

#define B_ 1024
#define T_ 512
#define K_ 48
#define NEG_ (-10000.0f)
#define START_ 46
#define STOP_ 47
#define NTHREADS 192
#define CHUNK 96

// scratch: packed v history, layout float4[(T/4) * K] per batch: entry (t>>2)*K + j
// holds v_t(j) for the 4 consecutive t in that quarter-group (~100.7 MB)
__device__ float4 g_v4[(size_t)B_ * (T_ / 4) * K_];

__device__ __forceinline__ float neg_inf() { return __int_as_float(0xff800000); }

// order-preserving float->uint map (no NaNs in our data)
__device__ __forceinline__ unsigned fmono(float x) {
    unsigned u = __float_as_uint(x);
    return (u & 0x80000000u) ? ~u : (u | 0x80000000u);
}
__device__ __forceinline__ float funmono(unsigned k) {
    return __uint_as_float((k & 0x80000000u) ? (k & 0x7fffffffu) : ~k);
}

__global__ __launch_bounds__(NTHREADS, 6)
void crf_kernel(const float* __restrict__ feats,
                const float* __restrict__ trans,
                const int* __restrict__ tags,
                float* __restrict__ out)
{
    const int b    = blockIdx.x;
    const int tid  = threadIdx.x;
    const int j    = tid >> 2;     // state 0..47
    const int s    = tid & 3;      // slice 0..3 (p in [12s, 12s+12))
    const int lane = tid & 31;
    const int w    = tid >> 5;

    __shared__ float shTr[K_ * K_];          // masked transitions (backtrace/terminal)
    __shared__ float shA[2][K_];             // exp-domain forward (double buffered)
    __shared__ float shV[2][K_];             // viterbi scores     (double buffered)
    __shared__ float shRed[8];
    __shared__ float shChunk[25 * 192];      // backtrace staging (25 quarter-groups)

    const float* frow = feats + (size_t)b * (T_ * K_);
    const int*   trow = tags + b * T_;
    float4* gvb4 = g_v4 + (size_t)b * (T_ / 4) * K_;

    // ---- masked transition slice: registers (hot loop) + SMEM (cold paths) ----
    float E[12], Trr[12];
    #pragma unroll
    for (int i = 0; i < 12; i++) {
        int p = 12 * s + i;
        float v = trans[j * K_ + p];
        if (j == START_) v = NEG_;   // never INTO start
        if (p == STOP_)  v = NEG_;   // never OUT OF stop
        shTr[j * K_ + p] = v;
        Trr[i] = v;
        E[i] = __expf(v);            // exp(-10000) -> exactly 0
    }

    // ---- gold score (raw trans == masked on gold path) ----
    float gp = 0.f;
    for (int t = tid; t < T_; t += NTHREADS) {
        int tg = trow[t];
        int pv = (t == 0) ? START_ : trow[t - 1];
        gp += frow[t * K_ + tg] + trans[tg * K_ + pv];
    }
    #pragma unroll
    for (int o = 16; o; o >>= 1) gp += __shfl_xor_sync(~0u, gp, o);
    if (lane == 0) shRed[w] = gp;

    // ---- init recurrences ----
    if (tid < K_) {
        shA[0][tid] = (tid == START_) ? 1.0f : 0.0f;   // exp(alpha_init)
        shV[0][tid] = (tid == START_) ? 0.0f : NEG_;
    }
    __syncthreads();
    float gold = shRed[0] + shRed[1] + shRed[2] + shRed[3] + shRed[4] + shRed[5]
               + trans[STOP_ * K_ + trow[T_ - 1]];

    // ---- main recurrence: 1 sync/step, exp-domain forward, max-only viterbi ----
    double Md = 0.0;            // accumulated log of divided-out scale
    float scale = 1.0f;
    float emit_next = frow[j];
    float vh0 = 0.f, vh1 = 0.f, vh2 = 0.f, vh3 = 0.f;   // v history (s==0 lanes)

    #pragma unroll 4
    for (int t = 0; t < T_; t++) {
        float emit = emit_next;
        if (t < T_ - 1) emit_next = frow[(t + 1) * K_ + j];
        const int cur = t & 1, nxt = cur ^ 1;
        const float4* A4 = (const float4*)shA[cur];
        const float4* V4 = (const float4*)shV[cur];

        float4 a0 = A4[3 * s + 0], a1 = A4[3 * s + 1], a2 = A4[3 * s + 2];
        float4 v0 = V4[3 * s + 0], v1 = V4[3 * s + 1], v2 = V4[3 * s + 2];

        // split accumulators (shorter dep chains); max is order-insensitive
        float sA, sB, mA, mB;
        sA = E[0] * a0.x;             sB = E[1] * a0.y;
        sA = fmaf(E[2],  a0.z, sA);   sB = fmaf(E[3],  a0.w, sB);
        sA = fmaf(E[4],  a1.x, sA);   sB = fmaf(E[5],  a1.y, sB);
        sA = fmaf(E[6],  a1.z, sA);   sB = fmaf(E[7],  a1.w, sB);
        sA = fmaf(E[8],  a2.x, sA);   sB = fmaf(E[9],  a2.y, sB);
        sA = fmaf(E[10], a2.z, sA);   sB = fmaf(E[11], a2.w, sB);
        mA = v0.x + Trr[0];                    mB = v0.y + Trr[1];
        mA = fmaxf(mA, v0.z + Trr[2]);         mB = fmaxf(mB, v0.w + Trr[3]);
        mA = fmaxf(mA, v1.x + Trr[4]);         mB = fmaxf(mB, v1.y + Trr[5]);
        mA = fmaxf(mA, v1.z + Trr[6]);         mB = fmaxf(mB, v1.w + Trr[7]);
        mA = fmaxf(mA, v2.x + Trr[8]);         mB = fmaxf(mB, v2.y + Trr[9]);
        mA = fmaxf(mA, v2.z + Trr[10]);        mB = fmaxf(mB, v2.w + Trr[11]);
        float sum = sA + sB;
        float vb  = fmaxf(mA, mB);

        sum += __shfl_xor_sync(~0u, sum, 1);
        sum += __shfl_xor_sync(~0u, sum, 2);
        vb = fmaxf(vb, __shfl_xor_sync(~0u, vb, 1));
        vb = fmaxf(vb, __shfl_xor_sync(~0u, vb, 2));

        float anew = __expf(emit) * (sum * scale);
        float vnew = vb + emit;

        const bool resc = ((t & 3) == 3) && (t != T_ - 1);
        if (resc) {
            float am = anew;
            am = fmaxf(am, __shfl_xor_sync(~0u, am, 4));
            am = fmaxf(am, __shfl_xor_sync(~0u, am, 8));
            am = fmaxf(am, __shfl_xor_sync(~0u, am, 16));
            if (lane == 0) shRed[w] = am;
        }
        if (s == 0) {
            shA[nxt][j] = anew;
            shV[nxt][j] = vnew;
            switch (t & 3) {
                case 0: vh0 = vnew; break;
                case 1: vh1 = vnew; break;
                case 2: vh2 = vnew; break;
                default:
                    vh3 = vnew;
                    gvb4[(t >> 2) * K_ + j] = make_float4(vh0, vh1, vh2, vh3);
            }
        }
        __syncthreads();
        if (resc) {
            float mx = fmaxf(fmaxf(fmaxf(shRed[0], shRed[1]), fmaxf(shRed[2], shRed[3])),
                             fmaxf(shRed[4], shRed[5]));
            int e = (int)((__float_as_uint(mx) >> 23) & 255) - 127;
            scale = __uint_as_float((unsigned)(127 - e) << 23);  // exact 2^-e
            Md += (double)e * 0.6931471805599453;
        } else {
            scale = 1.0f;
        }
    }
    // final buffers are index 0 (after t=511: nxt==0)

    // ---- logZ = Md + log( sum_j a_j * exp(termTr_j) ) ----
    float contrib = 0.f;
    if (s == 0) {
        float tt = shTr[STOP_ * K_ + j];   // masked: j==STOP -> NEG -> exp=0
        contrib = shA[0][j] * __expf(tt);
    }
    #pragma unroll
    for (int o = 16; o; o >>= 1) contrib += __shfl_xor_sync(~0u, contrib, o);
    if (lane == 0) shRed[w] = contrib;
    __syncthreads();
    if (tid == 0) {
        float Z = shRed[0] + shRed[1] + shRed[2] + shRed[3] + shRed[4] + shRed[5];
        double logZ = Md + (double)logf(Z);
        out[b] = (float)(logZ - (double)gold);
    }

    // ---- viterbi terminal: first-argmax over 48 (exact, jnp semantics) ----
    int tag = 0;
    if (w == 0) {
        float x0 = shV[0][lane] + shTr[STOP_ * K_ + lane];
        float x1 = (lane < 16) ? shV[0][32 + lane] + shTr[STOP_ * K_ + 32 + lane]
                               : neg_inf();
        unsigned k0 = fmono(x0), k1 = fmono(x1);
        unsigned gm = __reduce_max_sync(~0u, (k0 > k1) ? k0 : k1);
        int cand = 1 << 30;
        if (k1 == gm) cand = 32 + lane;
        if (k0 == gm) cand = lane;      // lower p wins ties
        tag = __reduce_min_sync(~0u, cand);
        if (lane == 0) out[B_ + b] = funmono(gm);   // path_score = max(term)
    }

    // ---- backtrace: chunked SMEM staging of packed v history ----
    float* pout = out + 2 * B_ + (size_t)b * T_;
    const int NCH = (T_ + CHUNK - 1) / CHUNK;       // 6
    for (int c = NCH - 1; c >= 0; c--) {
        int lo = c * CHUNK;
        int hi = min(lo + CHUNK, T_);
        int r0 = max(lo - 1, 0);        // earliest v-row needed
        int r1 = hi - 2;                // latest v-row needed (t in [lo,hi): reads t-1)
        int qa = r0 >> 2;
        int qb = r1 >> 2;
        int n4 = (qb - qa + 1) * K_;
        const float4* src = gvb4 + qa * K_;
        float4* dst = (float4*)shChunk;
        for (int i = tid; i < n4; i += NTHREADS) dst[i] = src[i];
        __syncthreads();
        if (w == 0) {
            for (int t = hi - 1; t >= lo; t--) {
                if (lane == 0) pout[t] = (float)tag;
                float pv0, pv1;
                if (t == 0) {
                    pv0 = (lane == START_) ? 0.f : NEG_;
                    pv1 = (32 + lane == START_) ? 0.f : NEG_;
                } else {
                    int qrel = ((t - 1) >> 2) - qa;
                    int r = (t - 1) & 3;
                    const float* row = shChunk + qrel * 192 + r;
                    pv0 = row[lane * 4];
                    pv1 = (lane < 16) ? row[(32 + lane) * 4] : 0.f;
                }
                float x0 = pv0 + shTr[tag * K_ + lane];
                float x1 = (lane < 16) ? pv1 + shTr[tag * K_ + 32 + lane]
                                       : neg_inf();
                unsigned k0 = fmono(x0), k1 = fmono(x1);
                unsigned gm = __reduce_max_sync(~0u, (k0 > k1) ? k0 : k1);
                int cand = 1 << 30;
                if (k1 == gm) cand = 32 + lane;
                if (k0 == gm) cand = lane;
                tag = __reduce_min_sync(~0u, cand);
            }
        }
        __syncthreads();
    }
}

extern "C" void kernel_launch(void* const* d_in, const int* in_sizes, int n_in,
                              void* d_out, int out_size) {
    const float* feats = (const float*)d_in[0];
    const float* trans = (const float*)d_in[1];
    const int*   tags  = (const int*)d_in[2];
    crf_kernel<<<B_, NTHREADS>>>(feats, trans, tags, (float*)d_out);
}

// round 5
// speedup vs baseline: 2.0822x; 1.0998x over previous
#include <cuda_runtime.h>

#define B_ 1024
#define T_ 512
#define K_ 48
#define NEG_ (-10000.0f)
#define START_ 46
#define STOP_ 47
#define NTHREADS 192
#define CHUNK 64

// scratch: v history, row t = 12 float4 = v_t[0..47]  (~100.7 MB)
__device__ float4 g_v4[(size_t)B_ * T_ * (K_ / 4)];

__device__ __forceinline__ float neg_inf() { return __int_as_float(0xff800000); }

// order-preserving float->uint map (no NaNs in our data)
__device__ __forceinline__ unsigned fmono(float x) {
    unsigned u = __float_as_uint(x);
    return (u & 0x80000000u) ? ~u : (u | 0x80000000u);
}
__device__ __forceinline__ float funmono(unsigned k) {
    return __uint_as_float((k & 0x80000000u) ? (k & 0x7fffffffu) : ~k);
}

__global__ __launch_bounds__(NTHREADS, 7)
void crf_kernel(const float* __restrict__ feats,
                const float* __restrict__ trans,
                const int* __restrict__ tags,
                float* __restrict__ out)
{
    const int b    = blockIdx.x;
    const int tid  = threadIdx.x;
    const int j    = tid >> 2;     // state 0..47
    const int s    = tid & 3;      // slice 0..3 (p in [12s, 12s+12))
    const int lane = tid & 31;
    const int w    = tid >> 5;

    __shared__ float shTr[K_ * K_];          // masked transitions (cold paths)
    __shared__ float shA[2][K_];             // exp-domain forward (double buffered)
    __shared__ float shV[2][K_];             // viterbi scores     (double buffered)
    __shared__ float shRed[8];
    __shared__ float shChunk[CHUNK * K_];    // backtrace staging (64 rows)

    const float* frow = feats + (size_t)b * (T_ * K_);
    const int*   trow = tags + b * T_;
    float* gvb = (float*)(g_v4 + (size_t)b * T_ * (K_ / 4));

    // ---- masked transition slice: registers (hot loop) + SMEM (cold paths) ----
    float E[12], Trr[12];
    #pragma unroll
    for (int i = 0; i < 12; i++) {
        int p = 12 * s + i;
        float v = trans[j * K_ + p];
        if (j == START_) v = NEG_;   // never INTO start
        if (p == STOP_)  v = NEG_;   // never OUT OF stop
        shTr[j * K_ + p] = v;
        Trr[i] = v;
        E[i] = __expf(v);            // exp(-10000) -> exactly 0
    }

    // ---- gold score (raw trans == masked on gold path) ----
    float gp = 0.f;
    for (int t = tid; t < T_; t += NTHREADS) {
        int tg = trow[t];
        int pv = (t == 0) ? START_ : trow[t - 1];
        gp += frow[t * K_ + tg] + trans[tg * K_ + pv];
    }
    #pragma unroll
    for (int o = 16; o; o >>= 1) gp += __shfl_xor_sync(~0u, gp, o);
    if (lane == 0) shRed[w] = gp;

    // ---- init recurrences ----
    if (tid < K_) {
        shA[0][tid] = (tid == START_) ? 1.0f : 0.0f;   // exp(alpha_init)
        shV[0][tid] = (tid == START_) ? 0.0f : NEG_;
    }
    __syncthreads();
    float gold = shRed[0] + shRed[1] + shRed[2] + shRed[3] + shRed[4] + shRed[5]
               + trans[STOP_ * K_ + trow[T_ - 1]];

    // ---- main recurrence: 1 sync/step, exp-domain forward, max-only viterbi ----
    int esum = 0;               // accumulated base-2 exponent divided out
    float scale = 1.0f;
    float emit_next = frow[j];

    #pragma unroll 8
    for (int t = 0; t < T_; t++) {
        float emit = emit_next;
        if (t < T_ - 1) emit_next = frow[(t + 1) * K_ + j];
        const int cur = t & 1, nxt = cur ^ 1;
        const float4* A4 = (const float4*)shA[cur];
        const float4* V4 = (const float4*)shV[cur];

        float sA, sB, mA, mB;
        {   // chunk 0 (staggered loads keep live regs low)
            float4 a = A4[3 * s + 0]; float4 v = V4[3 * s + 0];
            sA = E[0] * a.x;             sB = E[1] * a.y;
            sA = fmaf(E[2], a.z, sA);    sB = fmaf(E[3], a.w, sB);
            mA = v.x + Trr[0];           mB = v.y + Trr[1];
            mA = fmaxf(mA, v.z + Trr[2]);  mB = fmaxf(mB, v.w + Trr[3]);
        }
        {   // chunk 1
            float4 a = A4[3 * s + 1]; float4 v = V4[3 * s + 1];
            sA = fmaf(E[4], a.x, sA);    sB = fmaf(E[5], a.y, sB);
            sA = fmaf(E[6], a.z, sA);    sB = fmaf(E[7], a.w, sB);
            mA = fmaxf(mA, v.x + Trr[4]);  mB = fmaxf(mB, v.y + Trr[5]);
            mA = fmaxf(mA, v.z + Trr[6]);  mB = fmaxf(mB, v.w + Trr[7]);
        }
        {   // chunk 2
            float4 a = A4[3 * s + 2]; float4 v = V4[3 * s + 2];
            sA = fmaf(E[8],  a.x, sA);   sB = fmaf(E[9],  a.y, sB);
            sA = fmaf(E[10], a.z, sA);   sB = fmaf(E[11], a.w, sB);
            mA = fmaxf(mA, v.x + Trr[8]);   mB = fmaxf(mB, v.y + Trr[9]);
            mA = fmaxf(mA, v.z + Trr[10]);  mB = fmaxf(mB, v.w + Trr[11]);
        }
        float sum = sA + sB;
        float vb  = fmaxf(mA, mB);
        sum += __shfl_xor_sync(~0u, sum, 1);
        vb = fmaxf(vb, __shfl_xor_sync(~0u, vb, 1));
        sum += __shfl_xor_sync(~0u, sum, 2);
        vb = fmaxf(vb, __shfl_xor_sync(~0u, vb, 2));

        float anew = __expf(emit) * (sum * scale);
        float vnew = vb + emit;

        const bool resc = ((t & 7) == 7) && (t != T_ - 1);
        if (resc) {
            float am = anew;
            am = fmaxf(am, __shfl_xor_sync(~0u, am, 4));
            am = fmaxf(am, __shfl_xor_sync(~0u, am, 8));
            am = fmaxf(am, __shfl_xor_sync(~0u, am, 16));
            if (lane == 0) shRed[w] = am;
        }
        if (s == 0) {
            shA[nxt][j] = anew;
            shV[nxt][j] = vnew;
            gvb[t * K_ + j] = vnew;       // stream v_t for backtrace
        }
        __syncthreads();
        if (resc) {
            float mx = fmaxf(fmaxf(fmaxf(shRed[0], shRed[1]), fmaxf(shRed[2], shRed[3])),
                             fmaxf(shRed[4], shRed[5]));
            int e = (int)((__float_as_uint(mx) >> 23) & 255) - 127;
            scale = __uint_as_float((unsigned)(127 - e) << 23);  // exact 2^-e
            esum += e;
        } else {
            scale = 1.0f;
        }
    }
    // final buffers are index 0 (after t=511: nxt==0)

    // ---- logZ = esum*ln2 + log( sum_j a_j * exp(termTr_j) ) ----
    float contrib = 0.f;
    if (s == 0) {
        float tt = shTr[STOP_ * K_ + j];   // masked: j==STOP -> NEG -> exp=0
        contrib = shA[0][j] * __expf(tt);
    }
    #pragma unroll
    for (int o = 16; o; o >>= 1) contrib += __shfl_xor_sync(~0u, contrib, o);
    if (lane == 0) shRed[w] = contrib;
    __syncthreads();
    if (tid == 0) {
        float Z = shRed[0] + shRed[1] + shRed[2] + shRed[3] + shRed[4] + shRed[5];
        double logZ = (double)esum * 0.6931471805599453 + (double)logf(Z);
        out[b] = (float)(logZ - (double)gold);
    }

    // ---- viterbi terminal: first-argmax over 48 (exact, jnp semantics) ----
    int tag = 0;
    if (w == 0) {
        float x0 = shV[0][lane] + shTr[STOP_ * K_ + lane];
        float x1 = (lane < 16) ? shV[0][32 + lane] + shTr[STOP_ * K_ + 32 + lane]
                               : neg_inf();
        unsigned k0 = fmono(x0), k1 = fmono(x1);
        unsigned gm = __reduce_max_sync(~0u, (k0 > k1) ? k0 : k1);
        int cand = 1 << 30;
        if (k1 == gm) cand = 32 + lane;
        if (k0 == gm) cand = lane;      // lower p wins ties
        tag = __reduce_min_sync(~0u, cand);
        if (lane == 0) out[B_ + b] = funmono(gm);   // path_score = max(term)
    }

    // ---- backtrace: chunked SMEM staging of v history, warp0 walks path ----
    float* pout = out + 2 * B_ + (size_t)b * T_;
    const int NCH = (T_ + CHUNK - 1) / CHUNK;       // 8
    for (int c = NCH - 1; c >= 0; c--) {
        int lo = c * CHUNK;
        int hi = lo + CHUNK;
        int base = lo - 1;
        int r0 = max(lo - 1, 0);        // earliest v-row needed
        int r1 = hi - 2;                // latest v-row needed
        int n4 = (r1 - r0 + 1) * (K_ / 4);
        const float4* src4 = (const float4*)(gvb + r0 * K_);
        float4* dst4 = (float4*)(shChunk + (r0 - base) * K_);
        for (int i = tid; i < n4; i += NTHREADS) dst4[i] = src4[i];
        __syncthreads();
        if (w == 0) {
            for (int t = hi - 1; t >= lo; t--) {
                if (lane == 0) pout[t] = (float)tag;
                float pv0, pv1;
                if (t == 0) {
                    pv0 = (lane == START_) ? 0.f : NEG_;
                    pv1 = (32 + lane == START_) ? 0.f : NEG_;
                } else {
                    const float* row = shChunk + (t - lo) * K_;   // row t-1
                    pv0 = row[lane];
                    pv1 = (lane < 16) ? row[32 + lane] : 0.f;
                }
                float x0 = pv0 + shTr[tag * K_ + lane];
                float x1 = (lane < 16) ? pv1 + shTr[tag * K_ + 32 + lane]
                                       : neg_inf();
                unsigned k0 = fmono(x0), k1 = fmono(x1);
                unsigned gm = __reduce_max_sync(~0u, (k0 > k1) ? k0 : k1);
                int cand = 1 << 30;
                if (k1 == gm) cand = 32 + lane;
                if (k0 == gm) cand = lane;
                tag = __reduce_min_sync(~0u, cand);
            }
        }
        __syncthreads();
    }
}

extern "C" void kernel_launch(void* const* d_in, const int* in_sizes, int n_in,
                              void* d_out, int out_size) {
    const float* feats = (const float*)d_in[0];
    const float* trans = (const float*)d_in[1];
    const int*   tags  = (const int*)d_in[2];
    crf_kernel<<<B_, NTHREADS>>>(feats, trans, tags, (float*)d_out);
}